// round 1
// baseline (speedup 1.0000x reference)
#include <cuda_runtime.h>
#include <cstdint>

// Problem constants (fixed shapes: points (4, 8192, 3) fp32)
#define BATCH     4
#define NPTS      8192
#define NN_SIZE   16
#define RADIUS2   0.25f
#define EPS_LOSS  1e-4f

#define TPB       64          // threads per block (one query per thread)
#define TILE      2048        // candidate tile in smem
#define NTILES    (NPTS / TILE)
#define GRID_X    (NPTS / TPB)          // 128
#define NBLOCKS   (GRID_X * BATCH)      // 512

__device__ float g_blocksums[NBLOCKS];

// Branchless sorted insert of v into ascending a[0..15], dropping a[15].
// ~46 issue slots; only executed when v < a[15].
__device__ __forceinline__ void sorted_insert16(float (&a)[16], float v) {
#pragma unroll
    for (int k = 15; k > 0; --k) {
        float prev = a[k - 1];
        float cand = fminf(v, a[k]);
        a[k] = (v < prev) ? prev : cand;
    }
    a[0] = fminf(a[0], v);
}

template <bool SELF_CHECK>
__device__ __forceinline__ void scan_tile(const float4* __restrict__ tile,
                                          float qx, float qy, float qz,
                                          int self_local, float (&a)[16]) {
#pragma unroll 4
    for (int j = 0; j < TILE; ++j) {
        float4 c = tile[j];
        float dx = qx - c.x;
        float dy = qy - c.y;
        float dz = qz - c.z;
        float d2 = fmaf(dx, dx, fmaf(dy, dy, dz * dz));
        if (SELF_CHECK) {
            if (j == self_local) d2 = 1e30f;
        }
        if (d2 < a[15]) {
            sorted_insert16(a, d2);
        }
    }
}

__global__ __launch_bounds__(TPB) void knn_repulsion_kernel(
    const float* __restrict__ pts) {
    __shared__ float4 tile[TILE];
    __shared__ float red[TPB];

    const int b   = blockIdx.y;
    const int q   = blockIdx.x * TPB + threadIdx.x;
    const float* base = pts + (size_t)b * NPTS * 3;

    const float qx = base[3 * q + 0];
    const float qy = base[3 * q + 1];
    const float qz = base[3 * q + 2];

    // top-16 smallest d^2, capped at RADIUS2 (entries >= RADIUS2 contribute 0)
    float a[16];
#pragma unroll
    for (int k = 0; k < 16; ++k) a[k] = RADIUS2;

    const int my_tile    = q / TILE;      // all queries of this block share one tile
    const int self_local = q % TILE;

    for (int t = 0; t < NTILES; ++t) {
        __syncthreads();   // protect previous tile until all threads done scanning
        const float* src = base + (size_t)t * TILE * 3;
        for (int i = threadIdx.x; i < TILE; i += TPB) {
            tile[i] = make_float4(src[3 * i + 0], src[3 * i + 1], src[3 * i + 2], 0.0f);
        }
        __syncthreads();

        if (t == my_tile) {
            scan_tile<true>(tile, qx, qy, qz, self_local, a);
        } else {
            scan_tile<false>(tile, qx, qy, qz, 0, a);
        }
    }

    // Per-thread loss partial: entries equal to the 0.25 sentinel are excluded
    // by the strict <, matching the reference's (distance2 < RADIUS2) mask.
    float s = 0.0f;
#pragma unroll
    for (int k = 0; k < 16; ++k) {
        if (a[k] < RADIUS2) s += rsqrtf(a[k] + EPS_LOSS);
    }

    // Block reduction (deterministic)
    red[threadIdx.x] = s;
    __syncthreads();
#pragma unroll
    for (int off = TPB / 2; off > 0; off >>= 1) {
        if (threadIdx.x < off) red[threadIdx.x] += red[threadIdx.x + off];
        __syncthreads();
    }
    if (threadIdx.x == 0) {
        g_blocksums[blockIdx.y * GRID_X + blockIdx.x] = red[0];
    }
}

__global__ __launch_bounds__(NBLOCKS) void final_reduce_kernel(float* __restrict__ out) {
    __shared__ float r[NBLOCKS];
    r[threadIdx.x] = g_blocksums[threadIdx.x];
    __syncthreads();
#pragma unroll
    for (int off = NBLOCKS / 2; off > 0; off >>= 1) {
        if (threadIdx.x < off) r[threadIdx.x] += r[threadIdx.x + off];
        __syncthreads();
    }
    if (threadIdx.x == 0) {
        out[0] = r[0] * (1.0f / (float)(BATCH * NPTS * NN_SIZE));
    }
}

extern "C" void kernel_launch(void* const* d_in, const int* in_sizes, int n_in,
                              void* d_out, int out_size) {
    (void)in_sizes; (void)n_in; (void)out_size;
    const float* pts = (const float*)d_in[0];
    float* out = (float*)d_out;

    dim3 grid(GRID_X, BATCH);
    knn_repulsion_kernel<<<grid, TPB>>>(pts);
    final_reduce_kernel<<<1, NBLOCKS>>>(out);
}

// round 3
// speedup vs baseline: 1.4474x; 1.4474x over previous
#include <cuda_runtime.h>
#include <cstdint>

// Fixed shapes: points (4, 8192, 3) fp32
#define BATCH     4
#define NPTS      8192
#define NN_SIZE   16
#define RADIUS2   0.25f
#define EPS_LOSS  1e-4f

#define SPLIT     4            // threads per query (candidate split)
#define TPB       256          // threads per block
#define QPB       (TPB / SPLIT)        // 64 queries per block
#define TILE      2048                  // candidates per smem tile
#define NTILES    (NPTS / TILE)         // 4
#define JPT       (TILE / SPLIT)        // 512 candidates per lane per tile
#define GRID_X    (NPTS / QPB)          // 128
#define NBLOCKS   (GRID_X * BATCH)      // 512
#define MROW      68                    // padded merge-row stride (floats)

__device__ float g_blocksums[NBLOCKS];

// Branchless sorted insert (ascending) of v into a[0..15], dropping a[15].
// new_a[k] = min(max(v, a[k-1]), a[k]).  31 FMNMX ops.
__device__ __forceinline__ void sorted_insert16(float (&a)[16], float v) {
#pragma unroll
    for (int k = 15; k > 0; --k) {
        a[k] = fminf(fmaxf(v, a[k - 1]), a[k]);
    }
    a[0] = fminf(a[0], v);
}

// Scan this lane's stride-SPLIT subset of a tile. e-space metric:
//   e = 0.5|c|^2 - q.c   (3 FMAs with negated query),  d^2 = qsq + 2e.
template <bool SELF>
__device__ __forceinline__ void scan_tile(const float4* __restrict__ tile,
                                          int s, float nqx, float nqy, float nqz,
                                          int self_jj, float (&a)[16]) {
#pragma unroll 8
    for (int j = 0; j < JPT; ++j) {
        float4 c = tile[(j << 2) + s];
        float e = fmaf(c.x, nqx, fmaf(c.y, nqy, fmaf(c.z, nqz, c.w)));
        bool ok = (e < a[15]);
        if (SELF) ok = ok && (j != self_jj);
        if (ok) sorted_insert16(a, e);
    }
}

__global__ __launch_bounds__(TPB) void knn_repulsion_kernel(
    const float* __restrict__ pts) {
    // Arena: tile (32 KB) is dead after the last scan; merge buffer (17 KB)
    // and reduction buffer (1 KB) alias it, separated by __syncthreads().
    __shared__ __align__(16) char arena[TILE * sizeof(float4)];   // 32 KB
    __shared__ float qsq_s[QPB];

    float4* tile = reinterpret_cast<float4*>(arena);
    float*  mbuf = reinterpret_cast<float*>(arena);                       // QPB*MROW = 17 KB
    float*  red  = reinterpret_cast<float*>(arena + QPB * MROW * sizeof(float)); // +1 KB

    const int t    = threadIdx.x;
    const int ql   = t >> 2;                      // local query 0..63
    const int s    = t & 3;                       // split lane 0..3
    const int b    = blockIdx.y;
    const int q    = blockIdx.x * QPB + ql;       // global query index
    const float* base = pts + (size_t)b * NPTS * 3;

    const float qx = base[3 * q + 0];
    const float qy = base[3 * q + 1];
    const float qz = base[3 * q + 2];
    const float qsq = qx * qx + qy * qy + qz * qz;
    const float nqx = -qx, nqy = -qy, nqz = -qz;
    const float ecap = 0.5f * (RADIUS2 - qsq);    // e-space radius cap

    if (s == 0) qsq_s[ql] = qsq;

    // capped top-16 in e-space (sentinel = ecap; entries == ecap contribute 0)
    float a[16];
#pragma unroll
    for (int k = 0; k < 16; ++k) a[k] = ecap;

    // Self-exclusion: all queries of this block live in one tile.
    const int self_tile = q / TILE;
    const int l         = q % TILE;
    const int self_jj   = (s == (l & 3)) ? (l >> 2) : -1;

    for (int tt = 0; tt < NTILES; ++tt) {
        __syncthreads();
        const float* src = base + (size_t)tt * TILE * 3;
        for (int i = t; i < TILE; i += TPB) {
            float x = src[3 * i + 0];
            float y = src[3 * i + 1];
            float z = src[3 * i + 2];
            float w = 0.5f * (x * x + y * y + z * z);
            tile[i] = make_float4(x, y, z, w);
        }
        __syncthreads();

        if (tt == self_tile) scan_tile<true >(tile, s, nqx, nqy, nqz, self_jj, a);
        else                 scan_tile<false>(tile, s, nqx, nqy, nqz, 0, a);
    }

    __syncthreads();   // tile dead; arena becomes merge buffer

    // Dump sorted sublists for the merge phase.
#pragma unroll
    for (int k = 0; k < 16; ++k) {
        mbuf[ql * MROW + (s << 4) + k] = a[k];
    }
    __syncthreads();

    // Threads 0..63 each merge the 4 sorted 16-lists of one query:
    // 16-step 4-way pointer merge, accumulating rsqrt(d^2+eps) for d^2 < R^2.
    float part = 0.0f;
    if (t < QPB) {
        const float* L    = &mbuf[t * MROW];
        const float  mq   = qsq_s[t];
        const float  mcap = 0.5f * (RADIUS2 - mq);
        int p0 = 0, p1 = 16, p2 = 32, p3 = 48;
        for (int it = 0; it < NN_SIZE; ++it) {
            float h0 = L[p0], h1 = L[p1], h2 = L[p2], h3 = L[p3];
            float m01 = fminf(h0, h1);
            float m23 = fminf(h2, h3);
            float m   = fminf(m01, m23);
            if (m >= mcap) break;          // remaining are sentinels / beyond radius
            part += rsqrtf(fmaf(2.0f, m, mq) + EPS_LOSS);
            if      (m == h0) ++p0;
            else if (m == h1) ++p1;
            else if (m == h2) ++p2;
            else              ++p3;
        }
    }

    __syncthreads();   // merge reads done before red[] aliasing writes

    // Deterministic block reduction.
    red[t] = part;
    __syncthreads();
#pragma unroll
    for (int off = TPB / 2; off > 0; off >>= 1) {
        if (t < off) red[t] += red[t + off];
        __syncthreads();
    }
    if (t == 0) g_blocksums[blockIdx.y * GRID_X + blockIdx.x] = red[0];
}

__global__ __launch_bounds__(NBLOCKS) void final_reduce_kernel(float* __restrict__ out) {
    __shared__ float r[NBLOCKS];
    r[threadIdx.x] = g_blocksums[threadIdx.x];
    __syncthreads();
#pragma unroll
    for (int off = NBLOCKS / 2; off > 0; off >>= 1) {
        if (threadIdx.x < off) r[threadIdx.x] += r[threadIdx.x + off];
        __syncthreads();
    }
    if (threadIdx.x == 0) {
        out[0] = r[0] * (1.0f / (float)(BATCH * NPTS * NN_SIZE));
    }
}

extern "C" void kernel_launch(void* const* d_in, const int* in_sizes, int n_in,
                              void* d_out, int out_size) {
    (void)in_sizes; (void)n_in; (void)out_size;
    const float* pts = (const float*)d_in[0];
    float* out = (float*)d_out;

    dim3 grid(GRID_X, BATCH);
    knn_repulsion_kernel<<<grid, TPB>>>(pts);
    final_reduce_kernel<<<1, NBLOCKS>>>(out);
}

// round 5
// speedup vs baseline: 3.3049x; 2.2834x over previous
#include <cuda_runtime.h>
#include <cstdint>

// Fixed shapes: points (4, 8192, 3) fp32
#define BATCH     4
#define NPTS      8192
#define NN_SIZE   16
#define RADIUS2   0.25f
#define EPS_LOSS  1e-4f

// Spatial grid: cell width == radius (0.5), domain [-5,5) clamped
#define GDIM      20
#define NCELLS    (GDIM * GDIM * GDIM)     // 8000
#define GMIN      (-5.0f)
#define INV_CW    2.0f

// Main kernel layout
#define SPLIT     4
#define TPB       128
#define QPB       (TPB / SPLIT)            // 32 queries per block
#define BPB       (NPTS / QPB)             // 256 blocks per batch
#define MROW      65                       // conflict-free merge-row stride

__device__ int    g_count [BATCH * NCELLS];
__device__ int    g_cursor[BATCH * NCELLS];
__device__ int    g_start [BATCH * (NCELLS + 1)];
__device__ float4 g_sorted[BATCH * NPTS];
__device__ int    g_sid   [BATCH * NPTS];       // sorted pos -> original index
__device__ float  g_loss  [BATCH * NPTS];       // per ORIGINAL index (deterministic)

__device__ __forceinline__ int cell_of(float x, float y, float z) {
    int cx = (int)floorf((x - GMIN) * INV_CW);
    int cy = (int)floorf((y - GMIN) * INV_CW);
    int cz = (int)floorf((z - GMIN) * INV_CW);
    cx = min(max(cx, 0), GDIM - 1);
    cy = min(max(cy, 0), GDIM - 1);
    cz = min(max(cz, 0), GDIM - 1);
    return (cz * GDIM + cy) * GDIM + cx;
}

__global__ void k_zero() {
    int i = blockIdx.x * blockDim.x + threadIdx.x;
    int n = BATCH * NCELLS;
    for (; i < n; i += gridDim.x * blockDim.x) {
        g_count[i] = 0;
        g_cursor[i] = 0;
    }
}

__global__ void k_count(const float* __restrict__ pts) {
    int i = blockIdx.x * blockDim.x + threadIdx.x;
    if (i >= BATCH * NPTS) return;
    int b = i / NPTS;
    float x = pts[3 * i + 0], y = pts[3 * i + 1], z = pts[3 * i + 2];
    atomicAdd(&g_count[b * NCELLS + cell_of(x, y, z)], 1);
}

// Exclusive prefix sum per batch (one block per batch).
__global__ void k_scan() {
    __shared__ int buf[1024];
    const int b = blockIdx.x;
    const int t = threadIdx.x;
    int carry = 0;
    for (int base = 0; base < NCELLS; base += 1024) {
        int idx = base + t;
        int v = (idx < NCELLS) ? g_count[b * NCELLS + idx] : 0;
        buf[t] = v;
        __syncthreads();
        // Hillis-Steele inclusive scan
        for (int off = 1; off < 1024; off <<= 1) {
            int add = (t >= off) ? buf[t - off] : 0;
            __syncthreads();
            buf[t] += add;
            __syncthreads();
        }
        if (idx < NCELLS) g_start[b * (NCELLS + 1) + idx] = carry + buf[t] - v;
        int total = buf[1023];
        __syncthreads();
        carry += total;
    }
    if (t == 0) g_start[b * (NCELLS + 1) + NCELLS] = carry;
}

__global__ void k_scatter(const float* __restrict__ pts) {
    int i = blockIdx.x * blockDim.x + threadIdx.x;
    if (i >= BATCH * NPTS) return;
    int b = i / NPTS;
    float x = pts[3 * i + 0], y = pts[3 * i + 1], z = pts[3 * i + 2];
    int c = cell_of(x, y, z);
    int r = atomicAdd(&g_cursor[b * NCELLS + c], 1);
    int pos = g_start[b * (NCELLS + 1) + c] + r;
    float w = 0.5f * (x * x + y * y + z * z);
    g_sorted[b * NPTS + pos] = make_float4(x, y, z, w);
    g_sid[b * NPTS + pos] = i - b * NPTS;
}

__global__ void k_dummy() {}   // steers ncu -s 5 onto k_main

// Branchless sorted insert (ascending), drop a[15].
__device__ __forceinline__ void sorted_insert16(float (&a)[16], float v) {
#pragma unroll
    for (int k = 15; k > 0; --k) {
        a[k] = fminf(fmaxf(v, a[k - 1]), a[k]);
    }
    a[0] = fminf(a[0], v);
}

__global__ __launch_bounds__(TPB) void k_main() {
    __shared__ float mbuf[QPB * MROW];
    __shared__ float qw_s[QPB];

    const int t  = threadIdx.x;
    const int ql = t >> 2;                  // local query 0..31
    const int s  = t & 3;                   // split lane 0..3
    const int b  = blockIdx.x / BPB;
    const int g  = (blockIdx.x % BPB) * QPB + ql;   // sorted query position

    const float4* __restrict__ spts = &g_sorted[b * NPTS];
    const int*    __restrict__ cst  = &g_start[b * (NCELLS + 1)];

    const float4 qp = spts[g];
    const float nqx = -qp.x, nqy = -qp.y, nqz = -qp.z;
    const float ecap = 0.5f * RADIUS2 - qp.w;       // e < ecap  <=>  d^2 < R^2
    if (s == 0) qw_s[ql] = qp.w;

    float a[16];
#pragma unroll
    for (int k = 0; k < 16; ++k) a[k] = ecap;

    // Query cell coords (identical fp formula as binning -> identical cell)
    int cx = (int)floorf((qp.x - GMIN) * INV_CW);
    int cy = (int)floorf((qp.y - GMIN) * INV_CW);
    int cz = (int)floorf((qp.z - GMIN) * INV_CW);
    cx = min(max(cx, 0), GDIM - 1);
    cy = min(max(cy, 0), GDIM - 1);
    cz = min(max(cz, 0), GDIM - 1);

    for (int dz = -1; dz <= 1; ++dz) {
        int nz = cz + dz;
        if ((unsigned)nz >= GDIM) continue;
        for (int dy = -1; dy <= 1; ++dy) {
            int ny = cy + dy;
            if ((unsigned)ny >= GDIM) continue;
            for (int dx = -1; dx <= 1; ++dx) {
                int nx = cx + dx;
                if ((unsigned)nx >= GDIM) continue;
                int nc = (nz * GDIM + ny) * GDIM + nx;
                int k0 = cst[nc];
                int k1 = cst[nc + 1];
                for (int k = k0 + s; k < k1; k += SPLIT) {
                    float4 cd = spts[k];
                    float e = fmaf(cd.x, nqx, fmaf(cd.y, nqy, fmaf(cd.z, nqz, cd.w)));
                    if (e < a[15] && k != g) {
                        sorted_insert16(a, e);
                    }
                }
            }
        }
    }

    // Dump 4 sorted 16-lists per query.
#pragma unroll
    for (int k = 0; k < 16; ++k) {
        mbuf[ql * MROW + (s << 4) + k] = a[k];
    }
    __syncthreads();

    // One thread per query: 16-step 4-way pointer merge, accumulate loss in
    // ascending-e order (deterministic: the top-16 multiset is order-independent).
    if (t < QPB) {
        const float* L   = &mbuf[t * MROW];
        const float  w   = qw_s[t];
        const float  cap = 0.5f * RADIUS2 - w;
        float part = 0.0f;
        int p0 = 0, p1 = 16, p2 = 32, p3 = 48;
#pragma unroll 1
        for (int it = 0; it < NN_SIZE; ++it) {
            float h0 = L[p0], h1 = L[p1], h2 = L[p2], h3 = L[p3];
            float m = fminf(fminf(h0, h1), fminf(h2, h3));
            if (m >= cap) break;           // rest are sentinels / out of radius
            // d^2 = 2*(w + e)
            part += rsqrtf(fmaf(2.0f, w + m, EPS_LOSS));
            if      (m == h0) ++p0;
            else if (m == h1) ++p1;
            else if (m == h2) ++p2;
            else              ++p3;
        }
        int gq  = (blockIdx.x % BPB) * QPB + t;
        int oid = g_sid[b * NPTS + gq];
        g_loss[b * NPTS + oid] = part;
    }
}

// Deterministic fixed-order reduction of 32768 per-query losses.
__global__ __launch_bounds__(1024) void k_final(float* __restrict__ out) {
    __shared__ float r[1024];
    const int t = threadIdx.x;
    float s = 0.0f;
#pragma unroll
    for (int i = 0; i < (BATCH * NPTS) / 1024; ++i) {
        s += g_loss[i * 1024 + t];
    }
    r[t] = s;
    __syncthreads();
#pragma unroll
    for (int off = 512; off > 0; off >>= 1) {
        if (t < off) r[t] += r[t + off];
        __syncthreads();
    }
    if (t == 0) out[0] = r[0] * (1.0f / (float)(BATCH * NPTS * NN_SIZE));
}

extern "C" void kernel_launch(void* const* d_in, const int* in_sizes, int n_in,
                              void* d_out, int out_size) {
    (void)in_sizes; (void)n_in; (void)out_size;
    const float* pts = (const float*)d_in[0];
    float* out = (float*)d_out;

    const int npts_total = BATCH * NPTS;

    k_zero   <<<64, 256>>>();                              // launch 0
    k_count  <<<(npts_total + 255) / 256, 256>>>(pts);     // launch 1
    k_scan   <<<BATCH, 1024>>>();                          // launch 2
    k_scatter<<<(npts_total + 255) / 256, 256>>>(pts);     // launch 3
    k_dummy  <<<1, 32>>>();                                // launch 4 (ncu steering)
    k_main   <<<BATCH * BPB, TPB>>>();                     // launch 5 <- profiled
    k_final  <<<1, 1024>>>(out);                           // launch 6
}

// round 6
// speedup vs baseline: 4.3600x; 1.3193x over previous
#include <cuda_runtime.h>
#include <cstdint>

// Fixed shapes: points (4, 8192, 3) fp32
#define BATCH     4
#define NPTS      8192
#define NN_SIZE   16
#define RADIUS2   0.25f
#define EPS_LOSS  1e-4f

// Spatial grid: cell width == radius (0.5), domain [-5,5) clamped
#define GDIM      20
#define NCELLS    (GDIM * GDIM * GDIM)     // 8000
#define GMIN      (-5.0f)
#define INV_CW    2.0f
#define CW        0.5f

// Main kernel layout
#define SPLIT     4
#define TPB       128
#define QPB       (TPB / SPLIT)            // 32 queries per block
#define BPB       (NPTS / QPB)             // 256 blocks per batch
#define MROW      65                       // conflict-free merge-row stride

// Scan kernel layout
#define SCAN_T    256
#define CPT       32                       // cells per thread (256*32 = 8192 >= 8000)

__device__ int    g_count [BATCH * NCELLS];
__device__ int    g_start [BATCH * NCELLS];   // exclusive prefix; becomes END after scatter
__device__ float4 g_sorted[BATCH * NPTS];
__device__ int    g_sid   [BATCH * NPTS];     // sorted pos -> original index
__device__ float  g_loss  [BATCH * NPTS];     // per ORIGINAL index (deterministic)

__device__ __forceinline__ int cell_of(float x, float y, float z) {
    int cx = (int)floorf((x - GMIN) * INV_CW);
    int cy = (int)floorf((y - GMIN) * INV_CW);
    int cz = (int)floorf((z - GMIN) * INV_CW);
    cx = min(max(cx, 0), GDIM - 1);
    cy = min(max(cy, 0), GDIM - 1);
    cz = min(max(cz, 0), GDIM - 1);
    return (cz * GDIM + cy) * GDIM + cx;
}

__global__ void k_zero() {
    int i = blockIdx.x * blockDim.x + threadIdx.x;
    for (; i < BATCH * NCELLS; i += gridDim.x * blockDim.x) g_count[i] = 0;
}

__global__ void k_count(const float* __restrict__ pts) {
    int i = blockIdx.x * blockDim.x + threadIdx.x;
    if (i >= BATCH * NPTS) return;
    int b = i / NPTS;
    float x = pts[3 * i + 0], y = pts[3 * i + 1], z = pts[3 * i + 2];
    atomicAdd(&g_count[b * NCELLS + cell_of(x, y, z)], 1);
}

// Register-blocked exclusive scan: one block per batch, 256 thr x 32 cells.
__global__ __launch_bounds__(SCAN_T) void k_scan() {
    __shared__ int wsum[SCAN_T / 32];
    const int b = blockIdx.x;
    const int t = threadIdx.x;
    const int lane = t & 31, warp = t >> 5;
    const int base = t * CPT;

    int v[CPT];
    int tot = 0;
#pragma unroll
    for (int i = 0; i < CPT; ++i) {
        int c = base + i;
        v[i] = (c < NCELLS) ? g_count[b * NCELLS + c] : 0;
        tot += v[i];
    }
    // warp inclusive scan of per-thread totals
    int inc = tot;
#pragma unroll
    for (int off = 1; off < 32; off <<= 1) {
        int n = __shfl_up_sync(0xffffffffu, inc, off);
        if (lane >= off) inc += n;
    }
    if (lane == 31) wsum[warp] = inc;
    __syncthreads();
    if (warp == 0 && lane < SCAN_T / 32) {
        int w = wsum[lane];
#pragma unroll
        for (int off = 1; off < SCAN_T / 32; off <<= 1) {
            int n = __shfl_up_sync(0xffu, w, off);
            if (lane >= off) w += n;
        }
        wsum[lane] = w;
    }
    __syncthreads();
    int excl = inc - tot + (warp ? wsum[warp - 1] : 0);
#pragma unroll
    for (int i = 0; i < CPT; ++i) {
        int c = base + i;
        if (c < NCELLS) g_start[b * NCELLS + c] = excl;
        excl += v[i];
    }
}

// Scatter; atomically consumes g_start so that afterwards g_start[c] == end[c].
__global__ void k_scatter(const float* __restrict__ pts) {
    int i = blockIdx.x * blockDim.x + threadIdx.x;
    if (i >= BATCH * NPTS) return;
    int b = i / NPTS;
    float x = pts[3 * i + 0], y = pts[3 * i + 1], z = pts[3 * i + 2];
    int c = cell_of(x, y, z);
    int pos = atomicAdd(&g_start[b * NCELLS + c], 1);
    float w = 0.5f * (x * x + y * y + z * z);
    g_sorted[b * NPTS + pos] = make_float4(x, y, z, w);
    g_sid[b * NPTS + pos] = i - b * NPTS;
}

__global__ void k_dummy() {}   // steers ncu -s 5 onto k_main

// Branchless sorted insert (ascending), drop a[15].
__device__ __forceinline__ void sorted_insert16(float (&a)[16], float v) {
#pragma unroll
    for (int k = 15; k > 0; --k) {
        a[k] = fminf(fmaxf(v, a[k - 1]), a[k]);
    }
    a[0] = fminf(a[0], v);
}

// Scan one contiguous candidate run [k0, k1), this lane takes k0+s, +SPLIT, ...
template <bool SELF>
__device__ __forceinline__ void scan_run(const float4* __restrict__ spts,
                                         int k0, int k1, int s, int g,
                                         float nqx, float nqy, float nqz,
                                         float (&a)[16]) {
    for (int k = k0 + s; k < k1; k += SPLIT) {
        float4 cd = spts[k];
        float e = fmaf(cd.x, nqx, fmaf(cd.y, nqy, fmaf(cd.z, nqz, cd.w)));
        bool ok = (e < a[15]);
        if (SELF) ok = ok && (k != g);
        if (ok) sorted_insert16(a, e);
    }
}

__global__ __launch_bounds__(TPB) void k_main() {
    __shared__ float mbuf[QPB * MROW];
    __shared__ float qw_s[QPB];

    const int t  = threadIdx.x;
    const int ql = t >> 2;                  // local query 0..31
    const int s  = t & 3;                   // split lane 0..3
    const int b  = blockIdx.x / BPB;
    const int g  = (blockIdx.x % BPB) * QPB + ql;   // sorted query position

    const float4* __restrict__ spts = &g_sorted[b * NPTS];
    const int*    __restrict__ cend = &g_start[b * NCELLS];   // end offsets

    const float4 qp = spts[g];
    const float nqx = -qp.x, nqy = -qp.y, nqz = -qp.z;
    const float ecap = 0.5f * RADIUS2 - qp.w;       // e < ecap  <=>  d^2 < R^2
    if (s == 0) qw_s[ql] = qp.w;

    float a[16];
#pragma unroll
    for (int k = 0; k < 16; ++k) a[k] = ecap;

    // Query cell coords (identical fp formula as binning -> identical cell)
    int cx = (int)floorf((qp.x - GMIN) * INV_CW);
    int cy = (int)floorf((qp.y - GMIN) * INV_CW);
    int cz = (int)floorf((qp.z - GMIN) * INV_CW);
    cx = min(max(cx, 0), GDIM - 1);
    cy = min(max(cy, 0), GDIM - 1);
    cz = min(max(cz, 0), GDIM - 1);

    // In-cell fractional position for slab distances
    const float fy = qp.y - (GMIN + (float)cy * CW);
    const float fz = qp.z - (GMIN + (float)cz * CW);

    const int x0 = max(cx - 1, 0);
    const int x1 = min(cx + 1, GDIM - 1);

#pragma unroll
    for (int dz = -1; dz <= 1; ++dz) {
        int nz = cz + dz;
        if ((unsigned)nz >= GDIM) continue;
        float zd = (dz == 0) ? 0.0f : ((dz < 0) ? fz : (CW - fz));
        float zd2 = zd * zd;
#pragma unroll
        for (int dy = -1; dy <= 1; ++dy) {
            int ny = cy + dy;
            if ((unsigned)ny >= GDIM) continue;
            float yd = (dy == 0) ? 0.0f : ((dy < 0) ? fy : (CW - fy));
            if (fmaf(yd, yd, zd2) >= RADIUS2) continue;   // exact row prune
            int row = (nz * GDIM + ny) * GDIM;
            int c0 = row + x0;
            int c1 = row + x1;
            int k0 = (c0 == 0) ? 0 : cend[c0 - 1];
            int k1 = cend[c1];
            if (dy == 0 && dz == 0)
                scan_run<true >(spts, k0, k1, s, g, nqx, nqy, nqz, a);
            else
                scan_run<false>(spts, k0, k1, s, g, nqx, nqy, nqz, a);
        }
    }

    // Dump 4 sorted 16-lists per query.
#pragma unroll
    for (int k = 0; k < 16; ++k) {
        mbuf[ql * MROW + (s << 4) + k] = a[k];
    }
    __syncthreads();

    // One thread per query: 16-step 4-way pointer merge, accumulate loss in
    // ascending-e order (deterministic: top-16 multiset is order-independent).
    if (t < QPB) {
        const float* L   = &mbuf[t * MROW];
        const float  w   = qw_s[t];
        const float  cap = 0.5f * RADIUS2 - w;
        float part = 0.0f;
        int p0 = 0, p1 = 16, p2 = 32, p3 = 48;
#pragma unroll 1
        for (int it = 0; it < NN_SIZE; ++it) {
            float h0 = L[p0], h1 = L[p1], h2 = L[p2], h3 = L[p3];
            float m = fminf(fminf(h0, h1), fminf(h2, h3));
            if (m >= cap) break;           // rest are sentinels / out of radius
            part += rsqrtf(fmaf(2.0f, w + m, EPS_LOSS));   // d^2 = 2*(w+e)
            if      (m == h0) ++p0;
            else if (m == h1) ++p1;
            else if (m == h2) ++p2;
            else              ++p3;
        }
        int gq  = (blockIdx.x % BPB) * QPB + t;
        int oid = g_sid[b * NPTS + gq];
        g_loss[b * NPTS + oid] = part;
    }
}

// Deterministic fixed-order reduction of 32768 per-query losses.
__global__ __launch_bounds__(1024) void k_final(float* __restrict__ out) {
    __shared__ float r[1024];
    const int t = threadIdx.x;
    float s = 0.0f;
#pragma unroll
    for (int i = 0; i < (BATCH * NPTS) / 1024; ++i) {
        s += g_loss[i * 1024 + t];
    }
    r[t] = s;
    __syncthreads();
#pragma unroll
    for (int off = 512; off > 0; off >>= 1) {
        if (t < off) r[t] += r[t + off];
        __syncthreads();
    }
    if (t == 0) out[0] = r[0] * (1.0f / (float)(BATCH * NPTS * NN_SIZE));
}

extern "C" void kernel_launch(void* const* d_in, const int* in_sizes, int n_in,
                              void* d_out, int out_size) {
    (void)in_sizes; (void)n_in; (void)out_size;
    const float* pts = (const float*)d_in[0];
    float* out = (float*)d_out;

    const int npts_total = BATCH * NPTS;

    k_zero   <<<64, 256>>>();                              // launch 0
    k_count  <<<(npts_total + 255) / 256, 256>>>(pts);     // launch 1
    k_scan   <<<BATCH, SCAN_T>>>();                        // launch 2
    k_scatter<<<(npts_total + 255) / 256, 256>>>(pts);     // launch 3
    k_dummy  <<<1, 32>>>();                                // launch 4 (ncu steering)
    k_main   <<<BATCH * BPB, TPB>>>();                     // launch 5 <- profiled
    k_final  <<<1, 1024>>>(out);                           // launch 6
}